// round 16
// baseline (speedup 1.0000x reference)
#include <cuda_runtime.h>
#include <cuda_fp16.h>
#include <math.h>
#include <stdint.h>

#define BB 8
#define LL 2048
#define DIM 1024
#define ACT 256
#define HID 256
#define TOK (BB*LL)
#define EPSV 1e-6f
#define KSZ 5
#define NCHUNK 64
#define CHLEN 32

// ============ scratch ============
__device__ float g_xn [TOK*DIM];
__device__ float g_yf [TOK*DIM];
__device__ float g_y2f[TOK*DIM];
__device__ float g_h  [TOK*ACT];
__device__ float g_carry[BB*NCHUNK*ACT];
__device__ float g_F    [BB*NCHUNK*ACT];

__device__ __half g_a  [TOK*DIM];
__device__ __half g_xch[TOK*DIM];
__device__ __half g_yh [TOK*DIM];
__device__ __half g_y2h[TOK*DIM];
__device__ __half g_gh [TOK*HID];
__device__ __half g_pw[DIM*DIM];
__device__ __half g_w1[DIM*DIM];
__device__ __half g_w2[DIM*DIM];
__device__ __half g_dn[HID*DIM];
__device__ __half g_up[DIM*HID];

__device__ __forceinline__ uint32_t smem_u32(const void* p) {
    uint32_t a;
    asm("{ .reg .u64 t; cvta.to.shared.u64 t, %1; cvt.u32.u64 %0, t; }" : "=r"(a) : "l"(p));
    return a;
}
#define CP_ASYNC16(sa, g) \
    asm volatile("cp.async.cg.shared.global [%0], [%1], 16;" :: "r"(sa), "l"(g))
#define CP_COMMIT() asm volatile("cp.async.commit_group;")
#define CP_WAIT(n)  asm volatile("cp.async.wait_group %0;" :: "n"(n))
#define LDMX4(r0, r1, r2, r3, addr) \
    asm volatile("ldmatrix.sync.aligned.m8n8.x4.shared.b16 {%0,%1,%2,%3}, [%4];" \
        : "=r"(r0), "=r"(r1), "=r"(r2), "=r"(r3) : "r"(addr))
#define MMA_F16(d, a, b) \
    asm volatile("mma.sync.aligned.m16n8k16.row.col.f32.f16.f16.f32 " \
        "{%0,%1,%2,%3}, {%4,%5,%6,%7}, {%8,%9}, {%0,%1,%2,%3};" \
        : "+f"((d)[0]), "+f"((d)[1]), "+f"((d)[2]), "+f"((d)[3]) \
        : "r"((a)[0]), "r"((a)[1]), "r"((a)[2]), "r"((a)[3]), "r"((b)[0]), "r"((b)[1]))

// ============ convert all weights ============
__global__ void cvt_all_k(const float* __restrict__ pw, const float* __restrict__ w1,
                          const float* __restrict__ w2, const float* __restrict__ dn,
                          const float* __restrict__ up) {
    int i = blockIdx.x * blockDim.x + threadIdx.x;
    const int S1 = DIM*DIM, S2 = 2*DIM*DIM, S3 = 3*DIM*DIM, S4 = 3*DIM*DIM + HID*DIM;
    if (i < S1)            g_pw[i]      = __float2half_rn(pw[i]);
    else if (i < S2)       g_w1[i - S1] = __float2half_rn(w1[i - S1]);
    else if (i < S3)       g_w2[i - S2] = __float2half_rn(w2[i - S2]);
    else if (i < S4)       g_dn[i - S3] = __float2half_rn(dn[i - S3]);
    else                   g_up[i - S4] = __float2half_rn(up[i - S4]);
}

// ============ elementwise ============
__global__ void rmsnorm_k(const float* __restrict__ x, const float* __restrict__ w) {
    int tok = blockIdx.x;
    const float4* xr = (const float4*)(x + (size_t)tok * DIM);
    float4 v = xr[threadIdx.x];
    float ss = v.x*v.x + v.y*v.y + v.z*v.z + v.w*v.w;
    #pragma unroll
    for (int o = 16; o; o >>= 1) ss += __shfl_xor_sync(0xffffffffu, ss, o);
    __shared__ float red[8];
    if ((threadIdx.x & 31) == 0) red[threadIdx.x >> 5] = ss;
    __syncthreads();
    float tot = 0.f;
    #pragma unroll
    for (int i = 0; i < 8; i++) tot += red[i];
    float inv = rsqrtf(tot * (1.0f / DIM) + EPSV);
    float4 wv = ((const float4*)w)[threadIdx.x];
    float4 o;
    o.x = v.x * inv * wv.x; o.y = v.y * inv * wv.y;
    o.z = v.z * inv * wv.z; o.w = v.w * inv * wv.w;
    ((float4*)g_xn)[(size_t)tok * (DIM/4) + threadIdx.x] = o;
}

__global__ void conv_k(const float* __restrict__ dw_w, const float* __restrict__ dw_b) {
    int idx = blockIdx.x * blockDim.x + threadIdx.x;
    int c   = idx & (DIM - 1);
    int tok = idx >> 10;
    int t   = tok & (LL - 1);
    float acc = dw_b[c];
    #pragma unroll
    for (int k = 0; k < KSZ; k++) {
        int tt = t + k - 2;
        if (tt >= 0 && tt < LL)
            acc += g_xn[idx + (k - 2) * DIM] * dw_w[c * KSZ + k];
    }
    g_xch[idx] = __float2half_rn(acc);
}

__global__ void rec1_k(const float* __restrict__ alpha, const float* __restrict__ beta) {
    int b = blockIdx.x / NCHUNK, j = blockIdx.x % NCHUNK;
    int c = threadIdx.x;
    float al = alpha[c], be = beta[c];
    float h = 0.f;
    int t0 = j * CHLEN;
    const float* src = g_xn + ((size_t)(b * LL + t0)) * DIM + c;
    float*       dst = g_h  + ((size_t)(b * LL + t0)) * ACT + c;
    #pragma unroll 8
    for (int i = 0; i < CHLEN; i++) {
        h = al * h + be * src[(size_t)i * DIM];
        dst[(size_t)i * ACT] = h;
    }
    g_carry[(b * NCHUNK + j) * ACT + c] = h;
}

__global__ void rec2_k(const float* __restrict__ alpha) {
    int b = blockIdx.x, c = threadIdx.x;
    float aC = powf(alpha[c], (float)CHLEN);
    float car[NCHUNK];
    #pragma unroll
    for (int j = 0; j < NCHUNK; j++)
        car[j] = g_carry[(b * NCHUNK + j) * ACT + c];
    float F = 0.f;
    #pragma unroll
    for (int j = 0; j < NCHUNK; j++) {
        g_F[(b * NCHUNK + j) * ACT + c] = F;
        F = aC * F + car[j];
    }
}

__global__ void rec3_k(const float* __restrict__ alpha) {
    int b = blockIdx.x / NCHUNK, j = blockIdx.x % NCHUNK;
    if (j == 0) return;
    int c = threadIdx.x;
    float inc = g_F[(b * NCHUNK + j) * ACT + c];
    float al = alpha[c];
    float m = inc * al;
    float* dst = g_h + ((size_t)(b * LL + j * CHLEN)) * ACT + c;
    #pragma unroll 8
    for (int i = 0; i < CHLEN; i++) {
        dst[(size_t)i * ACT] += m;
        m *= al;
    }
}

// ============ HMMA fp16 GEMM: BLK_K=64, 3-slot pipeline, wait(2) ============
#define BLK_K 64
#define PADK 72
#define TILE_B (128 * PADK * 2)          // 18432
#define BUF_B  (2 * TILE_B)              // 36864
#define NSTAGE 3
#define SMEM_G (NSTAGE * BUF_B)          // 110592

__device__ __forceinline__ void ld_tile(uint32_t dst, const __half* __restrict__ src,
                                        int ldK, int row0, int k0, int tid) {
    #pragma unroll
    for (int i = 0; i < 4; i++) {
        int c = tid + i * 256;
        int r = c >> 3, kc = (c & 7) * 8;
        const __half* g = src + (size_t)(row0 + r) * ldK + k0 + kc;
        CP_ASYNC16(dst + (r * PADK + kc) * 2, g);
    }
}

template<int EPI>
__global__ __launch_bounds__(256, 2) void hgemm(
    const __half* __restrict__ Ah, const __half* __restrict__ Bh,
    const float* __restrict__ bias, float* __restrict__ Cf,
    int N, int K, const float* __restrict__ addx)
{
    extern __shared__ __align__(128) char smem[];
    uint32_t su = smem_u32(smem);
    int tid = threadIdx.x;
    int wid = tid >> 5, lane = tid & 31;
    int warp_m = wid & 3, warp_n = wid >> 2;
    int bm = blockIdx.y * 128, bn = blockIdx.x * 128;
    int NS = K / BLK_K;

    float acc[2][8][4];
    #pragma unroll
    for (int i = 0; i < 2; i++)
        #pragma unroll
        for (int j = 0; j < 8; j++)
            #pragma unroll
            for (int f = 0; f < 4; f++) acc[i][j][f] = 0.f;

    // prefetch up to 3 stages
    #pragma unroll
    for (int p = 0; p < NSTAGE; p++) {
        if (p < NS) {
            uint32_t b0 = su + p * BUF_B;
            int k0 = p * BLK_K;
            ld_tile(b0,          Ah, K, bm, k0, tid);
            ld_tile(b0 + TILE_B, Bh, K, bn, k0, tid);
        }
        CP_COMMIT();
    }

    for (int s = 0; s < NS; s++) {
        int rem = NS - 1 - s;
        if (rem >= 2) CP_WAIT(2); else if (rem == 1) CP_WAIT(1); else CP_WAIT(0);
        __syncthreads();

        uint32_t base = su + (s % NSTAGE) * BUF_B;
        #pragma unroll
        for (int kk = 0; kk < 4; kk++) {
            int k0 = kk * 16;
            uint32_t a_h[2][4];
            int arow = warp_m * 32 + (lane & 15);
            int acol = k0 + (lane >> 4) * 8;
            #pragma unroll
            for (int i = 0; i < 2; i++) {
                uint32_t ad = base + (((arow + i * 16) * PADK + acol) << 1);
                LDMX4(a_h[i][0], a_h[i][1], a_h[i][2], a_h[i][3], ad);
            }
            uint32_t b_h[8][2];
            int l8 = lane & 7, quad = lane >> 3;
            int brow_off = ((quad & 2) << 2) + l8;
            int bcol = k0 + ((quad & 1) << 3);
            #pragma unroll
            for (int j2 = 0; j2 < 4; j2++) {
                int brow = warp_n * 64 + j2 * 16 + brow_off;
                uint32_t bd = base + TILE_B + ((brow * PADK + bcol) << 1);
                uint32_t r0, r1, r2, r3;
                LDMX4(r0, r1, r2, r3, bd);
                b_h[2*j2][0] = r0;   b_h[2*j2][1] = r1;
                b_h[2*j2+1][0] = r2; b_h[2*j2+1][1] = r3;
            }
            #pragma unroll
            for (int i = 0; i < 2; i++)
                #pragma unroll
                for (int j = 0; j < 8; j++)
                    MMA_F16(acc[i][j], a_h[i], b_h[j]);
        }
        __syncthreads();
        if (s + NSTAGE < NS) {
            uint32_t nb = su + ((s + NSTAGE) % NSTAGE) * BUF_B;
            int k0 = (s + NSTAGE) * BLK_K;
            ld_tile(nb,          Ah, K, bm, k0, tid);
            ld_tile(nb + TILE_B, Bh, K, bn, k0, tid);
            CP_COMMIT();
        } else {
            CP_COMMIT();
        }
    }

    int g = lane >> 2, t4 = lane & 3;
    #pragma unroll
    for (int i = 0; i < 2; i++) {
        #pragma unroll
        for (int j = 0; j < 8; j++) {
            #pragma unroll
            for (int half = 0; half < 2; half++) {
                int m = bm + warp_m * 32 + i * 16 + g + half * 8;
                int n = bn + warp_n * 64 + j * 8 + 2 * t4;
                float v0 = acc[i][j][2 * half]     + bias[n];
                float v1 = acc[i][j][2 * half + 1] + bias[n + 1];
                if (EPI == 0) {
                    size_t o = (size_t)m * DIM + n;
                    v0 += (n     < ACT) ? g_h[(size_t)m * ACT + n]     : g_xn[o];
                    v1 += (n + 1 < ACT) ? g_h[(size_t)m * ACT + n + 1] : g_xn[o + 1];
                    *(float2*)&g_yf[o] = make_float2(v0, v1);
                    *(__half2*)&g_yh[o] = __floats2half2_rn(v0, v1);
                } else if (EPI == 1) {
                    *(__half2*)&g_a[(size_t)m * DIM + n] = __floats2half2_rn(v0, v1);
                } else if (EPI == 2) {
                    v0 = 0.5f * v0 * (1.f + erff(v0 * 0.70710678118654752f));
                    v1 = 0.5f * v1 * (1.f + erff(v1 * 0.70710678118654752f));
                    size_t o = (size_t)m * HID + n;
                    *(__half2*)&g_gh[o] = __floats2half2_rn(v0, v1);
                } else if (EPI == 3) {
                    size_t o = (size_t)m * DIM + n;
                    v0 += g_y2f[o]     + addx[o];
                    v1 += g_y2f[o + 1] + addx[o + 1];
                    *(float2*)&Cf[o] = make_float2(v0, v1);
                } else {
                    size_t o = (size_t)m * DIM + n;
                    __half2 ah = *(__half2*)&g_a[o];
                    float a0 = __half2float(ah.x), a1 = __half2float(ah.y);
                    float s0 = 1.f / (1.f + __expf(-a0));
                    float s1 = 1.f / (1.f + __expf(-a1));
                    float r0 = g_yf[o]     + s0 * tanhf(v0);
                    float r1 = g_yf[o + 1] + s1 * tanhf(v1);
                    *(float2*)&g_y2f[o] = make_float2(r0, r1);
                    *(__half2*)&g_y2h[o] = __floats2half2_rn(r0, r1);
                }
            }
        }
    }
}

// ============ launch ============
extern "C" void kernel_launch(void* const* d_in, const int* in_sizes, int n_in,
                              void* d_out, int out_size) {
    const float* x      = (const float*)d_in[0];
    const float* norm_w = (const float*)d_in[1];
    const float* dw_w   = (const float*)d_in[2];
    const float* dw_b   = (const float*)d_in[3];
    const float* pw_w   = (const float*)d_in[4];
    const float* pw_b   = (const float*)d_in[5];
    const float* alpha  = (const float*)d_in[6];
    const float* beta   = (const float*)d_in[7];
    const float* W1_w   = (const float*)d_in[8];
    const float* W1_b   = (const float*)d_in[9];
    const float* W2_w   = (const float*)d_in[10];
    const float* W2_b   = (const float*)d_in[11];
    const float* down_w = (const float*)d_in[12];
    const float* down_b = (const float*)d_in[13];
    const float* up_w   = (const float*)d_in[14];
    const float* up_b   = (const float*)d_in[15];
    float* out = (float*)d_out;

    cudaFuncSetAttribute(hgemm<0>, cudaFuncAttributeMaxDynamicSharedMemorySize, SMEM_G);
    cudaFuncSetAttribute(hgemm<1>, cudaFuncAttributeMaxDynamicSharedMemorySize, SMEM_G);
    cudaFuncSetAttribute(hgemm<2>, cudaFuncAttributeMaxDynamicSharedMemorySize, SMEM_G);
    cudaFuncSetAttribute(hgemm<3>, cudaFuncAttributeMaxDynamicSharedMemorySize, SMEM_G);
    cudaFuncSetAttribute(hgemm<4>, cudaFuncAttributeMaxDynamicSharedMemorySize, SMEM_G);

    static cudaStream_t s_rec = nullptr, s_cvt = nullptr;
    static cudaEvent_t ev_root = nullptr, ev_norm = nullptr, ev_rec = nullptr, ev_cvt = nullptr;
    if (s_rec == nullptr) {
        cudaStreamCreateWithFlags(&s_rec, cudaStreamNonBlocking);
        cudaStreamCreateWithFlags(&s_cvt, cudaStreamNonBlocking);
        cudaEventCreateWithFlags(&ev_root, cudaEventDisableTiming);
        cudaEventCreateWithFlags(&ev_norm, cudaEventDisableTiming);
        cudaEventCreateWithFlags(&ev_rec,  cudaEventDisableTiming);
        cudaEventCreateWithFlags(&ev_cvt,  cudaEventDisableTiming);
    }

    __half *p_xch, *p_yh, *p_y2h, *p_gh, *p_pw, *p_w1, *p_w2, *p_dn, *p_up;
    cudaGetSymbolAddress((void**)&p_xch, g_xch);
    cudaGetSymbolAddress((void**)&p_yh,  g_yh);
    cudaGetSymbolAddress((void**)&p_y2h, g_y2h);
    cudaGetSymbolAddress((void**)&p_gh,  g_gh);
    cudaGetSymbolAddress((void**)&p_pw,  g_pw);
    cudaGetSymbolAddress((void**)&p_w1,  g_w1);
    cudaGetSymbolAddress((void**)&p_w2,  g_w2);
    cudaGetSymbolAddress((void**)&p_dn,  g_dn);
    cudaGetSymbolAddress((void**)&p_up,  g_up);

    // fork: cvt_all fully independent
    cudaEventRecord(ev_root, 0);
    cudaStreamWaitEvent(s_cvt, ev_root, 0);
    int ncvt = 3 * DIM * DIM + 2 * HID * DIM;
    cvt_all_k<<<(ncvt + 255) / 256, 256, 0, s_cvt>>>(pw_w, W1_w, W2_w, down_w, up_w);
    cudaEventRecord(ev_cvt, s_cvt);

    // main: rmsnorm, then fork rec chain vs conv
    rmsnorm_k<<<TOK, 256>>>(x, norm_w);
    cudaEventRecord(ev_norm, 0);
    cudaStreamWaitEvent(s_rec, ev_norm, 0);
    rec1_k<<<BB * NCHUNK, ACT, 0, s_rec>>>(alpha, beta);
    rec2_k<<<BB, ACT, 0, s_rec>>>(alpha);
    rec3_k<<<BB * NCHUNK, ACT, 0, s_rec>>>(alpha);
    cudaEventRecord(ev_rec, s_rec);

    conv_k<<<TOK * DIM / 256, 256>>>(dw_w, dw_b);

    // join before GEMMs
    cudaStreamWaitEvent(0, ev_rec, 0);
    cudaStreamWaitEvent(0, ev_cvt, 0);

    dim3 gBig(DIM / 128, TOK / 128);
    dim3 gDown(HID / 128, TOK / 128);

    hgemm<0><<<gBig, 256, SMEM_G>>>(p_xch, p_pw, pw_b, nullptr, DIM, DIM, nullptr);
    hgemm<1><<<gBig, 256, SMEM_G>>>(p_yh, p_w1, W1_b, nullptr, DIM, DIM, nullptr);
    hgemm<4><<<gBig, 256, SMEM_G>>>(p_yh, p_w2, W2_b, nullptr, DIM, DIM, nullptr);
    hgemm<2><<<gDown, 256, SMEM_G>>>(p_y2h, p_dn, down_b, nullptr, HID, DIM, nullptr);
    hgemm<3><<<gBig, 256, SMEM_G>>>(p_gh, p_up, up_b, out, DIM, HID, x);
}

// round 17
// speedup vs baseline: 1.1007x; 1.1007x over previous
#include <cuda_runtime.h>
#include <cuda_fp16.h>
#include <math.h>
#include <stdint.h>

#define BB 8
#define LL 2048
#define DIM 1024
#define ACT 256
#define HID 256
#define TOK (BB*LL)
#define EPSV 1e-6f
#define KSZ 5
#define NCHUNK 64
#define CHLEN 32

// ============ scratch ============
__device__ float g_xn [TOK*DIM];
__device__ float g_y2f[TOK*DIM];
__device__ float g_h  [TOK*ACT];
__device__ float g_carry[BB*NCHUNK*ACT];
__device__ float g_F    [BB*NCHUNK*ACT];

__device__ __half g_a  [TOK*DIM];
__device__ __half g_xch[TOK*DIM];
__device__ __half g_yh [TOK*DIM];
__device__ __half g_y2h[TOK*DIM];
__device__ __half g_gh [TOK*HID];
__device__ __half g_pw[DIM*DIM];
__device__ __half g_w1[DIM*DIM];
__device__ __half g_w2[DIM*DIM];
__device__ __half g_dn[HID*DIM];
__device__ __half g_up[DIM*HID];

__device__ __forceinline__ uint32_t smem_u32(const void* p) {
    uint32_t a;
    asm("{ .reg .u64 t; cvta.to.shared.u64 t, %1; cvt.u32.u64 %0, t; }" : "=r"(a) : "l"(p));
    return a;
}
#define CP_ASYNC16(sa, g) \
    asm volatile("cp.async.cg.shared.global [%0], [%1], 16;" :: "r"(sa), "l"(g))
#define CP_COMMIT() asm volatile("cp.async.commit_group;")
#define CP_WAIT(n)  asm volatile("cp.async.wait_group %0;" :: "n"(n))
#define LDMX4(r0, r1, r2, r3, addr) \
    asm volatile("ldmatrix.sync.aligned.m8n8.x4.shared.b16 {%0,%1,%2,%3}, [%4];" \
        : "=r"(r0), "=r"(r1), "=r"(r2), "=r"(r3) : "r"(addr))
#define MMA_F16(d, a, b) \
    asm volatile("mma.sync.aligned.m16n8k16.row.col.f32.f16.f16.f32 " \
        "{%0,%1,%2,%3}, {%4,%5,%6,%7}, {%8,%9}, {%0,%1,%2,%3};" \
        : "+f"((d)[0]), "+f"((d)[1]), "+f"((d)[2]), "+f"((d)[3]) \
        : "r"((a)[0]), "r"((a)[1]), "r"((a)[2]), "r"((a)[3]), "r"((b)[0]), "r"((b)[1]))

// ============ convert all weights ============
__global__ void cvt_all_k(const float* __restrict__ pw, const float* __restrict__ w1,
                          const float* __restrict__ w2, const float* __restrict__ dn,
                          const float* __restrict__ up) {
    int i = blockIdx.x * blockDim.x + threadIdx.x;
    const int S1 = DIM*DIM, S2 = 2*DIM*DIM, S3 = 3*DIM*DIM, S4 = 3*DIM*DIM + HID*DIM;
    if (i < S1)            g_pw[i]      = __float2half_rn(pw[i]);
    else if (i < S2)       g_w1[i - S1] = __float2half_rn(w1[i - S1]);
    else if (i < S3)       g_w2[i - S2] = __float2half_rn(w2[i - S2]);
    else if (i < S4)       g_dn[i - S3] = __float2half_rn(dn[i - S3]);
    else                   g_up[i - S4] = __float2half_rn(up[i - S4]);
}

// ============ elementwise ============
__global__ void rmsnorm_k(const float* __restrict__ x, const float* __restrict__ w) {
    int tok = blockIdx.x;
    const float4* xr = (const float4*)(x + (size_t)tok * DIM);
    float4 v = xr[threadIdx.x];
    float ss = v.x*v.x + v.y*v.y + v.z*v.z + v.w*v.w;
    #pragma unroll
    for (int o = 16; o; o >>= 1) ss += __shfl_xor_sync(0xffffffffu, ss, o);
    __shared__ float red[8];
    if ((threadIdx.x & 31) == 0) red[threadIdx.x >> 5] = ss;
    __syncthreads();
    float tot = 0.f;
    #pragma unroll
    for (int i = 0; i < 8; i++) tot += red[i];
    float inv = rsqrtf(tot * (1.0f / DIM) + EPSV);
    float4 wv = ((const float4*)w)[threadIdx.x];
    float4 o;
    o.x = v.x * inv * wv.x; o.y = v.y * inv * wv.y;
    o.z = v.z * inv * wv.z; o.w = v.w * inv * wv.w;
    ((float4*)g_xn)[(size_t)tok * (DIM/4) + threadIdx.x] = o;
}

__global__ void conv_k(const float* __restrict__ dw_w, const float* __restrict__ dw_b) {
    int idx = blockIdx.x * blockDim.x + threadIdx.x;
    int c   = idx & (DIM - 1);
    int tok = idx >> 10;
    int t   = tok & (LL - 1);
    float acc = dw_b[c];
    #pragma unroll
    for (int k = 0; k < KSZ; k++) {
        int tt = t + k - 2;
        if (tt >= 0 && tt < LL)
            acc += g_xn[idx + (k - 2) * DIM] * dw_w[c * KSZ + k];
    }
    g_xch[idx] = __float2half_rn(acc);
}

__global__ void rec1_k(const float* __restrict__ alpha, const float* __restrict__ beta) {
    int b = blockIdx.x / NCHUNK, j = blockIdx.x % NCHUNK;
    int c = threadIdx.x;
    float al = alpha[c], be = beta[c];
    float h = 0.f;
    int t0 = j * CHLEN;
    const float* src = g_xn + ((size_t)(b * LL + t0)) * DIM + c;
    float*       dst = g_h  + ((size_t)(b * LL + t0)) * ACT + c;
    #pragma unroll 8
    for (int i = 0; i < CHLEN; i++) {
        h = al * h + be * src[(size_t)i * DIM];
        dst[(size_t)i * ACT] = h;
    }
    g_carry[(b * NCHUNK + j) * ACT + c] = h;
}

__global__ void rec2_k(const float* __restrict__ alpha) {
    int b = blockIdx.x, c = threadIdx.x;
    float aC = powf(alpha[c], (float)CHLEN);
    float car[NCHUNK];
    #pragma unroll
    for (int j = 0; j < NCHUNK; j++)
        car[j] = g_carry[(b * NCHUNK + j) * ACT + c];
    float F = 0.f;
    #pragma unroll
    for (int j = 0; j < NCHUNK; j++) {
        g_F[(b * NCHUNK + j) * ACT + c] = F;
        F = aC * F + car[j];
    }
}

__global__ void rec3_k(const float* __restrict__ alpha) {
    int b = blockIdx.x / NCHUNK, j = blockIdx.x % NCHUNK;
    if (j == 0) return;
    int c = threadIdx.x;
    float inc = g_F[(b * NCHUNK + j) * ACT + c];
    float al = alpha[c];
    float m = inc * al;
    float* dst = g_h + ((size_t)(b * LL + j * CHLEN)) * ACT + c;
    #pragma unroll 8
    for (int i = 0; i < CHLEN; i++) {
        dst[(size_t)i * ACT] += m;
        m *= al;
    }
}

// ============ HMMA fp16 GEMM: BLK_K=64, 2-slot pipeline (R15 champion) ============
#define BLK_K 64
#define PADK 72
#define TILE_B (128 * PADK * 2)          // 18432
#define BUF_B  (2 * TILE_B)              // 36864
#define NSTAGE 2
#define SMEM_G (NSTAGE * BUF_B)          // 73728

__device__ __forceinline__ void ld_tile(uint32_t dst, const __half* __restrict__ src,
                                        int ldK, int row0, int k0, int tid) {
    #pragma unroll
    for (int i = 0; i < 4; i++) {
        int c = tid + i * 256;
        int r = c >> 3, kc = (c & 7) * 8;
        const __half* g = src + (size_t)(row0 + r) * ldK + k0 + kc;
        CP_ASYNC16(dst + (r * PADK + kc) * 2, g);
    }
}

template<int EPI>
__global__ __launch_bounds__(256, 2) void hgemm(
    const __half* __restrict__ Ah, const __half* __restrict__ Bh,
    const float* __restrict__ bias, float* __restrict__ Cf,
    int N, int K, const float* __restrict__ addx)
{
    extern __shared__ __align__(128) char smem[];
    uint32_t su = smem_u32(smem);
    int tid = threadIdx.x;
    int wid = tid >> 5, lane = tid & 31;
    int warp_m = wid & 3, warp_n = wid >> 2;
    int bm = blockIdx.y * 128, bn = blockIdx.x * 128;
    int NS = K / BLK_K;

    float acc[2][8][4];
    #pragma unroll
    for (int i = 0; i < 2; i++)
        #pragma unroll
        for (int j = 0; j < 8; j++)
            #pragma unroll
            for (int f = 0; f < 4; f++) acc[i][j][f] = 0.f;

    // prefetch 2 stages
    #pragma unroll
    for (int p = 0; p < 2; p++) {
        uint32_t b0 = su + p * BUF_B;
        int k0 = p * BLK_K;
        ld_tile(b0,          Ah, K, bm, k0, tid);
        ld_tile(b0 + TILE_B, Bh, K, bn, k0, tid);
        CP_COMMIT();
    }

    for (int s = 0; s < NS; s++) {
        if (s + 1 < NS) CP_WAIT(1); else CP_WAIT(0);
        __syncthreads();

        uint32_t base = su + (s & 1) * BUF_B;
        #pragma unroll
        for (int kk = 0; kk < 4; kk++) {
            int k0 = kk * 16;
            uint32_t a_h[2][4];
            int arow = warp_m * 32 + (lane & 15);
            int acol = k0 + (lane >> 4) * 8;
            #pragma unroll
            for (int i = 0; i < 2; i++) {
                uint32_t ad = base + (((arow + i * 16) * PADK + acol) << 1);
                LDMX4(a_h[i][0], a_h[i][1], a_h[i][2], a_h[i][3], ad);
            }
            uint32_t b_h[8][2];
            int l8 = lane & 7, quad = lane >> 3;
            int brow_off = ((quad & 2) << 2) + l8;
            int bcol = k0 + ((quad & 1) << 3);
            #pragma unroll
            for (int j2 = 0; j2 < 4; j2++) {
                int brow = warp_n * 64 + j2 * 16 + brow_off;
                uint32_t bd = base + TILE_B + ((brow * PADK + bcol) << 1);
                uint32_t r0, r1, r2, r3;
                LDMX4(r0, r1, r2, r3, bd);
                b_h[2*j2][0] = r0;   b_h[2*j2][1] = r1;
                b_h[2*j2+1][0] = r2; b_h[2*j2+1][1] = r3;
            }
            #pragma unroll
            for (int i = 0; i < 2; i++)
                #pragma unroll
                for (int j = 0; j < 8; j++)
                    MMA_F16(acc[i][j], a_h[i], b_h[j]);
        }
        __syncthreads();
        if (s + 2 < NS) {
            uint32_t nb = su + (s & 1) * BUF_B;
            int k0 = (s + 2) * BLK_K;
            ld_tile(nb,          Ah, K, bm, k0, tid);
            ld_tile(nb + TILE_B, Bh, K, bn, k0, tid);
            CP_COMMIT();
        }
    }

    int g = lane >> 2, t4 = lane & 3;
    #pragma unroll
    for (int i = 0; i < 2; i++) {
        #pragma unroll
        for (int j = 0; j < 8; j++) {
            #pragma unroll
            for (int half = 0; half < 2; half++) {
                int m = bm + warp_m * 32 + i * 16 + g + half * 8;
                int n = bn + warp_n * 64 + j * 8 + 2 * t4;
                float v0 = acc[i][j][2 * half]     + bias[n];
                float v1 = acc[i][j][2 * half + 1] + bias[n + 1];
                if (EPI == 0) {
                    size_t o = (size_t)m * DIM + n;
                    v0 += (n     < ACT) ? g_h[(size_t)m * ACT + n]     : g_xn[o];
                    v1 += (n + 1 < ACT) ? g_h[(size_t)m * ACT + n + 1] : g_xn[o + 1];
                    *(__half2*)&g_yh[o] = __floats2half2_rn(v0, v1);
                } else if (EPI == 1) {
                    *(__half2*)&g_a[(size_t)m * DIM + n] = __floats2half2_rn(v0, v1);
                } else if (EPI == 2) {
                    v0 = 0.5f * v0 * (1.f + erff(v0 * 0.70710678118654752f));
                    v1 = 0.5f * v1 * (1.f + erff(v1 * 0.70710678118654752f));
                    size_t o = (size_t)m * HID + n;
                    *(__half2*)&g_gh[o] = __floats2half2_rn(v0, v1);
                } else if (EPI == 3) {
                    size_t o = (size_t)m * DIM + n;
                    v0 += g_y2f[o]     + addx[o];
                    v1 += g_y2f[o + 1] + addx[o + 1];
                    *(float2*)&Cf[o] = make_float2(v0, v1);
                } else {
                    size_t o = (size_t)m * DIM + n;
                    __half2 ah = *(__half2*)&g_a[o];
                    __half2 yh = *(__half2*)&g_yh[o];
                    float a0 = __half2float(ah.x), a1 = __half2float(ah.y);
                    float y0 = __half2float(yh.x), y1 = __half2float(yh.y);
                    float s0 = 1.f / (1.f + __expf(-a0));
                    float s1 = 1.f / (1.f + __expf(-a1));
                    float r0 = y0 + s0 * tanhf(v0);
                    float r1 = y1 + s1 * tanhf(v1);
                    *(float2*)&g_y2f[o] = make_float2(r0, r1);
                    *(__half2*)&g_y2h[o] = __floats2half2_rn(r0, r1);
                }
            }
        }
    }
}

// ============ launch ============
extern "C" void kernel_launch(void* const* d_in, const int* in_sizes, int n_in,
                              void* d_out, int out_size) {
    const float* x      = (const float*)d_in[0];
    const float* norm_w = (const float*)d_in[1];
    const float* dw_w   = (const float*)d_in[2];
    const float* dw_b   = (const float*)d_in[3];
    const float* pw_w   = (const float*)d_in[4];
    const float* pw_b   = (const float*)d_in[5];
    const float* alpha  = (const float*)d_in[6];
    const float* beta   = (const float*)d_in[7];
    const float* W1_w   = (const float*)d_in[8];
    const float* W1_b   = (const float*)d_in[9];
    const float* W2_w   = (const float*)d_in[10];
    const float* W2_b   = (const float*)d_in[11];
    const float* down_w = (const float*)d_in[12];
    const float* down_b = (const float*)d_in[13];
    const float* up_w   = (const float*)d_in[14];
    const float* up_b   = (const float*)d_in[15];
    float* out = (float*)d_out;

    cudaFuncSetAttribute(hgemm<0>, cudaFuncAttributeMaxDynamicSharedMemorySize, SMEM_G);
    cudaFuncSetAttribute(hgemm<1>, cudaFuncAttributeMaxDynamicSharedMemorySize, SMEM_G);
    cudaFuncSetAttribute(hgemm<2>, cudaFuncAttributeMaxDynamicSharedMemorySize, SMEM_G);
    cudaFuncSetAttribute(hgemm<3>, cudaFuncAttributeMaxDynamicSharedMemorySize, SMEM_G);
    cudaFuncSetAttribute(hgemm<4>, cudaFuncAttributeMaxDynamicSharedMemorySize, SMEM_G);

    static cudaStream_t s_rec = nullptr, s_cvt = nullptr;
    static cudaEvent_t ev_root = nullptr, ev_norm = nullptr, ev_rec = nullptr, ev_cvt = nullptr;
    if (s_rec == nullptr) {
        cudaStreamCreateWithFlags(&s_rec, cudaStreamNonBlocking);
        cudaStreamCreateWithFlags(&s_cvt, cudaStreamNonBlocking);
        cudaEventCreateWithFlags(&ev_root, cudaEventDisableTiming);
        cudaEventCreateWithFlags(&ev_norm, cudaEventDisableTiming);
        cudaEventCreateWithFlags(&ev_rec,  cudaEventDisableTiming);
        cudaEventCreateWithFlags(&ev_cvt,  cudaEventDisableTiming);
    }

    __half *p_xch, *p_yh, *p_y2h, *p_gh, *p_pw, *p_w1, *p_w2, *p_dn, *p_up;
    cudaGetSymbolAddress((void**)&p_xch, g_xch);
    cudaGetSymbolAddress((void**)&p_yh,  g_yh);
    cudaGetSymbolAddress((void**)&p_y2h, g_y2h);
    cudaGetSymbolAddress((void**)&p_gh,  g_gh);
    cudaGetSymbolAddress((void**)&p_pw,  g_pw);
    cudaGetSymbolAddress((void**)&p_w1,  g_w1);
    cudaGetSymbolAddress((void**)&p_w2,  g_w2);
    cudaGetSymbolAddress((void**)&p_dn,  g_dn);
    cudaGetSymbolAddress((void**)&p_up,  g_up);

    // fork: cvt_all fully independent
    cudaEventRecord(ev_root, 0);
    cudaStreamWaitEvent(s_cvt, ev_root, 0);
    int ncvt = 3 * DIM * DIM + 2 * HID * DIM;
    cvt_all_k<<<(ncvt + 255) / 256, 256, 0, s_cvt>>>(pw_w, W1_w, W2_w, down_w, up_w);
    cudaEventRecord(ev_cvt, s_cvt);

    // main: rmsnorm, then fork rec chain vs conv
    rmsnorm_k<<<TOK, 256>>>(x, norm_w);
    cudaEventRecord(ev_norm, 0);
    cudaStreamWaitEvent(s_rec, ev_norm, 0);
    rec1_k<<<BB * NCHUNK, ACT, 0, s_rec>>>(alpha, beta);
    rec2_k<<<BB, ACT, 0, s_rec>>>(alpha);
    rec3_k<<<BB * NCHUNK, ACT, 0, s_rec>>>(alpha);
    cudaEventRecord(ev_rec, s_rec);

    conv_k<<<TOK * DIM / 256, 256>>>(dw_w, dw_b);

    // join before GEMMs
    cudaStreamWaitEvent(0, ev_rec, 0);
    cudaStreamWaitEvent(0, ev_cvt, 0);

    dim3 gBig(DIM / 128, TOK / 128);
    dim3 gDown(HID / 128, TOK / 128);

    hgemm<0><<<gBig, 256, SMEM_G>>>(p_xch, p_pw, pw_b, nullptr, DIM, DIM, nullptr);
    hgemm<1><<<gBig, 256, SMEM_G>>>(p_yh, p_w1, W1_b, nullptr, DIM, DIM, nullptr);
    hgemm<4><<<gBig, 256, SMEM_G>>>(p_yh, p_w2, W2_b, nullptr, DIM, DIM, nullptr);
    hgemm<2><<<gDown, 256, SMEM_G>>>(p_y2h, p_dn, down_b, nullptr, HID, DIM, nullptr);
    hgemm<3><<<gBig, 256, SMEM_G>>>(p_gh, p_up, up_b, out, DIM, HID, x);
}